// round 17
// baseline (speedup 1.0000x reference)
#include <cuda_runtime.h>

// GRU autoencoder: B=128, H=512, T=512 enc + 513 dec iterations.
// Persistent single kernel, 128 CTAs, CTA c owns hidden cols [4c,4c+4).
//
// R15 = R14's gate-split mainloop + R13's PROVEN threadfence barrier
// (R14 changed both at once and the container died; isolate the variable).
// Thread = (gate-half, k-octant, lane): 6 (enc) / 6-7 (dec) gate rows x
// 4 batches x 64 k. Each 16B weight LDS feeds 8 fma2 (LDS/thread 192->96).
// lin_W is row 12 of s_w.

#define HH   512
#define TT   512
#define BB   128
#define NBLK 128
#define COLS 4
#define NTH  512

typedef unsigned long long ull;

#define SMEM_FLOATS (13 * HH + 8 * 13 * BB)   // s_w(13 rows) + s_red[8][13][BB]
#define SMEM_BYTES  (SMEM_FLOATS * 4)

__device__ float4 g_hA[HH * BB / 4];     // slot m*BB+b = h[4m..4m+3][b]
__device__ float4 g_hB[HH * BB / 4];
__device__ unsigned long long g_arrive;  // monotonic; replay-safe
__device__ unsigned long long g_release;

// R13 barrier (5 consecutive passing benches) — unchanged.
__device__ __forceinline__ void grid_barrier() {
    __threadfence();
    __syncthreads();
    if (threadIdx.x == 0) {
        unsigned long long t = atomicAdd(&g_arrive, 1ULL) + 1ULL;
        unsigned long long phase = (t + (unsigned long long)(NBLK - 1)) / NBLK;
        if ((t % NBLK) == 0ULL) {
            atomicAdd(&g_release, 1ULL);
        } else {
            long long guard = 0;
            while (*(volatile unsigned long long*)&g_release < phase) {
                __nanosleep(20);
                if (++guard > 900000000LL) __trap();
            }
        }
        __threadfence();
    }
    __syncthreads();
}

__device__ __forceinline__ float sigf(float v) {
    return __fdividef(1.0f, 1.0f + __expf(-v));
}
__device__ __forceinline__ float ftanh(float v) {
    float e = __expf(-2.0f * v);
    return __fdividef(1.0f - e, 1.0f + e);
}

__device__ __forceinline__ ull pack2(float lo, float hi) {
    ull r;
    asm("mov.b64 %0, {%1, %2};" : "=l"(r) : "f"(lo), "f"(hi));
    return r;
}
__device__ __forceinline__ ull fma2(ull a, ull b, ull c) {
    ull d;
    asm("fma.rn.f32x2 %0, %1, %2, %3;" : "=l"(d) : "l"(a), "l"(b), "l"(c));
    return d;
}
__device__ __forceinline__ float red2(ull v) {
    float lo, hi;
    asm("mov.b64 {%0, %1}, %2;" : "=f"(lo), "=f"(hi) : "l"(v));
    return lo + hi;
}

// NR gate-row dots x 4 batches over a 64-k octant.
// acc[r][bi]; batches b = lane + 32*bi; rows rowbase..rowbase+NR-1.
template<int NR>
__device__ __forceinline__ void dots(ull (*acc)[4], const float* s_w,
                                     int rowbase, int m0, int lane,
                                     const float4* __restrict__ hcur) {
    #pragma unroll 2
    for (int grp = 0; grp < 8; ++grp) {      // 2 float4-slots (8 k) per group
        const int m = m0 + grp * 2;
        float4 f0[4], f1[4];
        #pragma unroll
        for (int bi = 0; bi < 4; ++bi) {
            f0[bi] = __ldcg(hcur + (m + 0) * BB + lane + 32 * bi);
            f1[bi] = __ldcg(hcur + (m + 1) * BB + lane + 32 * bi);
        }
        ull lo0[4], hi0[4], lo1[4], hi1[4];
        #pragma unroll
        for (int bi = 0; bi < 4; ++bi) {
            lo0[bi] = pack2(f0[bi].x, f0[bi].y);
            hi0[bi] = pack2(f0[bi].z, f0[bi].w);
            lo1[bi] = pack2(f1[bi].x, f1[bi].y);
            hi1[bi] = pack2(f1[bi].z, f1[bi].w);
        }
        #pragma unroll
        for (int r = 0; r < NR; ++r) {
            const ulonglong2* wr = (const ulonglong2*)&s_w[(rowbase + r) * HH + 4 * m];
            ulonglong2 w0 = wr[0], w1 = wr[1];
            #pragma unroll
            for (int bi = 0; bi < 4; ++bi) {
                ull t = acc[r][bi];
                t = fma2(lo0[bi], w0.x, t);
                t = fma2(hi0[bi], w0.y, t);
                t = fma2(lo1[bi], w1.x, t);
                t = fma2(hi1[bi], w1.y, t);
                acc[r][bi] = t;
            }
        }
    }
}

template<int NR>
__device__ __forceinline__ void publish(ull (*acc)[4], float* s_red,
                                        int oct, int rowbase, int lane) {
    #pragma unroll
    for (int r = 0; r < NR; ++r) {
        float* base = &s_red[(oct * 13 + rowbase + r) * BB + lane];
        #pragma unroll
        for (int bi = 0; bi < 4; ++bi) base[32 * bi] = red2(acc[r][bi]);
    }
}

__global__ void __launch_bounds__(NTH, 1)
gru_ae(const float* __restrict__ x,
       const float* __restrict__ eWi, const float* __restrict__ eWh,
       const float* __restrict__ ebi, const float* __restrict__ ebh,
       const float* __restrict__ dWi, const float* __restrict__ dWh,
       const float* __restrict__ dbi, const float* __restrict__ dbh,
       const float* __restrict__ lW,  const float* __restrict__ lb,
       float* __restrict__ out)
{
    extern __shared__ __align__(16) float smem[];
    float* s_w   = smem;                 // 13*HH: rows 0..11 Wh (jj*3+gate), 12 = lin
    float* s_red = smem + 13 * HH;       // [oct 8][13][BB]

    __shared__ float s_wi[12], s_bi[12], s_bh[12];
    __shared__ float s_lb;

    const int tid  = threadIdx.x;
    const int bx   = blockIdx.x;
    const int j0   = bx * COLS;

    // mainloop mapping
    const int lane = tid & 31;
    const int wrp  = tid >> 5;           // 0..15
    const int gh   = wrp & 1;            // gate-half: rows 6*gh ..
    const int oct  = wrp >> 1;           // k-octant 0..7
    const int m0   = oct * 16;           // 16 float4-slots = 64 k

    // epilogue mapping
    const int eb   = tid & (BB - 1);
    const int ec   = tid >> 7;           // col 0..3
    const int g0   = 3 * ec;

    // ---- encoder weights -> SMEM (rows 0..11 Wh gather, row 12 = lin) ----
    for (int i = tid; i < 13 * (HH / 4); i += NTH) {
        int row = i / (HH / 4), kk = i % (HH / 4);
        float4 v;
        if (row < 12) {
            int grow = (row % 3) * HH + (j0 + row / 3);
            v = ((const float4*)eWh)[grow * (HH / 4) + kk];
        } else {
            v = ((const float4*)lW)[kk];
        }
        ((float4*)s_w)[row * (HH / 4) + kk] = v;
    }
    if (tid < 12) {
        int grow = (tid % 3) * HH + (j0 + tid / 3);
        s_wi[tid] = eWi[grow];
        s_bi[tid] = ebi[grow];
        s_bh[tid] = ebh[grow];
    }
    if (tid == 0) s_lb = lb[0];

    if (tid < BB) g_hA[bx * BB + tid] = make_float4(0.f, 0.f, 0.f, 0.f);

    grid_barrier();

    float4* hcur = g_hA;
    float4* hnxt = g_hB;

    // ================= encoder: 512 steps =================
    for (int t = 0; t < TT; ++t) {
        float hp = __ldcg((const float*)(hcur + bx * BB + eb) + ec);
        float xv = x[eb * TT + t];

        ull acc[6][4];
        #pragma unroll
        for (int r = 0; r < 6; ++r)
            #pragma unroll
            for (int bi = 0; bi < 4; ++bi) acc[r][bi] = 0ULL;

        dots<6>(acc, s_w, 6 * gh, m0, lane, hcur);
        publish<6>(acc, s_red, oct, 6 * gh, lane);
        __syncthreads();

        // epilogue: thread owns (col=ec, batch=eb)
        {
            float ar = 0.f, az = 0.f, an = 0.f;
            #pragma unroll
            for (int q = 0; q < 8; ++q) {
                ar += s_red[(q * 13 + g0 + 0) * BB + eb];
                az += s_red[(q * 13 + g0 + 1) * BB + eb];
                an += s_red[(q * 13 + g0 + 2) * BB + eb];
            }
            float r = sigf(fmaf(xv, s_wi[g0 + 0], s_bi[g0 + 0] + s_bh[g0 + 0]) + ar);
            float z = sigf(fmaf(xv, s_wi[g0 + 1], s_bi[g0 + 1] + s_bh[g0 + 1]) + az);
            float n = ftanh(fmaf(xv, s_wi[g0 + 2], s_bi[g0 + 2]) + r * (an + s_bh[g0 + 2]));
            ((float*)(hnxt + bx * BB + eb))[ec] = (1.0f - z) * n + z * hp;
        }

        grid_barrier();
        float4* tc = hcur; hcur = hnxt; hnxt = tc;
    }

    // ---- swap rows 0..11 to decoder weights (row 12 = lin unchanged) ----
    for (int i = tid; i < 12 * (HH / 4); i += NTH) {
        int row = i / (HH / 4), kk = i % (HH / 4);
        int grow = (row % 3) * HH + (j0 + row / 3);
        ((float4*)s_w)[row * (HH / 4) + kk] = ((const float4*)dWh)[grow * (HH / 4) + kk];
    }
    if (tid < 12) {
        int grow = (tid % 3) * HH + (j0 + tid / 3);
        s_wi[tid] = dWi[grow];
        s_bi[tid] = dbi[grow];
        s_bh[tid] = dbh[grow];
    }
    __syncthreads();

    // ================= decoder: i = 0..512 =================
    // y_i = h_i @ lin_W.T + lin_b (row 12, redundant per CTA). Emit y_i at
    // out[:, T-i] for i>=1. For i<512 also compute h_{i+1}.
    for (int i = 0; i <= TT; ++i) {
        float hp = __ldcg((const float*)(hcur + bx * BB + eb) + ec);

        if (gh == 0) {
            ull acc[6][4];
            #pragma unroll
            for (int r = 0; r < 6; ++r)
                #pragma unroll
                for (int bi = 0; bi < 4; ++bi) acc[r][bi] = 0ULL;
            dots<6>(acc, s_w, 0, m0, lane, hcur);
            publish<6>(acc, s_red, oct, 0, lane);
        } else {
            ull acc[7][4];
            #pragma unroll
            for (int r = 0; r < 7; ++r)
                #pragma unroll
                for (int bi = 0; bi < 4; ++bi) acc[r][bi] = 0ULL;
            dots<7>(acc, s_w, 6, m0, lane, hcur);      // rows 6..12 (incl lin)
            publish<7>(acc, s_red, oct, 6, lane);
        }
        __syncthreads();

        {
            float y = s_lb;
            #pragma unroll
            for (int q = 0; q < 8; ++q) y += s_red[(q * 13 + 12) * BB + eb];
            if (i >= 1 && bx == 0 && ec == 0) out[eb * TT + (TT - i)] = y;
            if (i < TT) {
                float ar = 0.f, az = 0.f, an = 0.f;
                #pragma unroll
                for (int q = 0; q < 8; ++q) {
                    ar += s_red[(q * 13 + g0 + 0) * BB + eb];
                    az += s_red[(q * 13 + g0 + 1) * BB + eb];
                    an += s_red[(q * 13 + g0 + 2) * BB + eb];
                }
                float r = sigf(fmaf(y, s_wi[g0 + 0], s_bi[g0 + 0] + s_bh[g0 + 0]) + ar);
                float z = sigf(fmaf(y, s_wi[g0 + 1], s_bi[g0 + 1] + s_bh[g0 + 1]) + az);
                float n = ftanh(fmaf(y, s_wi[g0 + 2], s_bi[g0 + 2]) + r * (an + s_bh[g0 + 2]));
                ((float*)(hnxt + bx * BB + eb))[ec] = (1.0f - z) * n + z * hp;
            }
        }

        if (i < TT) {
            grid_barrier();
            float4* tc = hcur; hcur = hnxt; hnxt = tc;
        }
    }
}

extern "C" void kernel_launch(void* const* d_in, const int* in_sizes, int n_in,
                              void* d_out, int out_size) {
    cudaFuncSetAttribute(gru_ae, cudaFuncAttributeMaxDynamicSharedMemorySize,
                         SMEM_BYTES);
    gru_ae<<<NBLK, NTH, SMEM_BYTES>>>(
        (const float*)d_in[0],
        (const float*)d_in[1], (const float*)d_in[2],
        (const float*)d_in[3], (const float*)d_in[4],
        (const float*)d_in[5], (const float*)d_in[6],
        (const float*)d_in[7], (const float*)d_in[8],
        (const float*)d_in[9], (const float*)d_in[10],
        (float*)d_out);
}